// round 2
// baseline (speedup 1.0000x reference)
#include <cuda_runtime.h>
#include <math.h>

// ---------------------------------------------------------------------------
// PolyNetFP4Sim: x (B,1) -> 64 -> 64 -> 32 -> 1 MLP with FP4-quantized weights.
// Because the input is a SCALAR per sample, the entire network is a smooth 1-D
// function f(x). Strategy:
//   Kernel 1: tabulate f on a uniform grid (8192 pts over [-9,9]).
//   Kernel 2: per-sample 4-point cubic Lagrange interpolation (error O(h^4)).
// Out-of-range x (never occurs for N(0,1) with B=1M) falls back to direct eval.
// ---------------------------------------------------------------------------

#define TABLE_N 8192
#define XMIN    (-9.0f)
// H = 18/8192 = 9 * 2^-12, exactly representable; grid points exact in fp32.
#define H_STEP  (0.002197265625f)
#define INV_H   (455.11111111111111f)   // 8192/18

__device__ float g_table[TABLE_N];

__device__ __forceinline__ float quant4(float w) {
    if (w == 0.0f) return 0.0f;
    int e;
    float m = frexpf(fabsf(w), &e);             // m in [0.5, 1)
    int qe = e + 1;
    qe = qe < 0 ? 0 : (qe > 3 ? 3 : qe);
    float qm = (m >= 0.75f) ? 0.5f : 0.0f;      // mantissa bit
    float val = ldexpf((1.0f + qm) * 0.5f, qe - 1);
    return copysignf(val, w);
}

__device__ __forceinline__ float silu(float x) {
    return x / (1.0f + expf(-x));
}

// Full network evaluation from raw (unquantized) weights. Cold path only
// (|x| > ~8.99); never taken for the actual dataset but keeps us correct
// for any input. __noinline__ to keep it off the hot path.
__device__ __noinline__ float eval_full(
    float x,
    const float* w1, const float* b1,
    const float* w2, const float* b2,
    const float* w3, const float* b3,
    const float* w4, const float* b4)
{
    float h1[64], h2[64];
    for (int j = 0; j < 64; j++)
        h1[j] = silu(fmaf(x, quant4(w1[j]), b1[j]));
    for (int j = 0; j < 64; j++) {
        float a = b2[j];
        for (int k = 0; k < 64; k++)
            a = fmaf(h1[k], quant4(w2[j * 64 + k]), a);
        h2[j] = silu(a);
    }
    float acc = b4[0];
    for (int j = 0; j < 32; j++) {
        float a = b3[j];
        for (int k = 0; k < 64; k++)
            a = fmaf(h2[k], quant4(w3[j * 64 + k]), a);
        acc = fmaf(silu(a), quant4(w4[j]), acc);
    }
    return acc;
}

// ---------------------------------------------------------------------------
// Kernel 1: build table. One warp per table entry; 8 warps (256 thr) / block.
// Weights quantized into shared per block (redundant across blocks, trivial).
// w2/w3 stored TRANSPOSED [k][j] so lane j reads consecutive addresses
// (conflict-free); h values broadcast from per-warp shared rows.
// ---------------------------------------------------------------------------
__global__ void __launch_bounds__(256)
build_table_kernel(
    const float* __restrict__ w1, const float* __restrict__ b1,
    const float* __restrict__ w2, const float* __restrict__ b2,
    const float* __restrict__ w3, const float* __restrict__ b3,
    const float* __restrict__ w4, const float* __restrict__ b4)
{
    __shared__ float sw1[64], sb1[64], sb2[64], sb3[32], sw4[32];
    __shared__ float sw2T[64 * 64];   // [k][j]
    __shared__ float sw3T[64 * 32];   // [k][j]
    __shared__ float sh1[8][64];
    __shared__ float sh2[8][64];

    const int tid = threadIdx.x;

    for (int i = tid; i < 64; i += blockDim.x) {
        sw1[i] = quant4(w1[i]);
        sb1[i] = b1[i];
        sb2[i] = b2[i];
    }
    for (int i = tid; i < 32; i += blockDim.x) {
        sb3[i] = b3[i];
        sw4[i] = quant4(w4[i]);
    }
    for (int i = tid; i < 64 * 64; i += blockDim.x) {
        int j = i >> 6, k = i & 63;
        sw2T[k * 64 + j] = quant4(w2[i]);
    }
    for (int i = tid; i < 32 * 64; i += blockDim.x) {
        int j = i >> 6, k = i & 63;
        sw3T[k * 32 + j] = quant4(w3[i]);
    }
    __syncthreads();

    const int warp = tid >> 5;
    const int lane = tid & 31;
    const int entry = blockIdx.x * 8 + warp;
    if (entry >= TABLE_N) return;

    const float x = XMIN + (float)entry * H_STEP;

    // layer 1: 64 outputs, 2 per lane
    sh1[warp][lane]      = silu(fmaf(x, sw1[lane],      sb1[lane]));
    sh1[warp][lane + 32] = silu(fmaf(x, sw1[lane + 32], sb1[lane + 32]));
    __syncwarp();

    // layer 2: 64x64; lane j handles outputs j and j+32
    float a0 = sb2[lane];
    float a1 = sb2[lane + 32];
    #pragma unroll
    for (int k = 0; k < 64; k++) {
        float h = sh1[warp][k];                     // broadcast
        a0 = fmaf(h, sw2T[k * 64 + lane],      a0); // conflict-free
        a1 = fmaf(h, sw2T[k * 64 + lane + 32], a1);
    }
    sh2[warp][lane]      = silu(a0);
    sh2[warp][lane + 32] = silu(a1);
    __syncwarp();

    // layer 3: 32x64; lane j handles output j
    float c = sb3[lane];
    #pragma unroll
    for (int k = 0; k < 64; k++)
        c = fmaf(sh2[warp][k], sw3T[k * 32 + lane], c);
    float h3 = silu(c);

    // layer 4: dot(h3, w4) + b4 via warp reduction
    float p = h3 * sw4[lane];
    #pragma unroll
    for (int off = 16; off; off >>= 1)
        p += __shfl_xor_sync(0xffffffffu, p, off);

    if (lane == 0)
        g_table[entry] = p + b4[0];
}

// ---------------------------------------------------------------------------
// Kernel 2: apply. Table cached in shared; cubic Lagrange interpolation.
// ---------------------------------------------------------------------------
__global__ void __launch_bounds__(256)
apply_kernel(
    const float* __restrict__ x, float* __restrict__ out, int n,
    const float* __restrict__ w1, const float* __restrict__ b1,
    const float* __restrict__ w2, const float* __restrict__ b2,
    const float* __restrict__ w3, const float* __restrict__ b3,
    const float* __restrict__ w4, const float* __restrict__ b4)
{
    __shared__ float st[TABLE_N];
    {
        float4*       dst = reinterpret_cast<float4*>(st);
        const float4* src = reinterpret_cast<const float4*>(g_table);
        for (int i = threadIdx.x; i < TABLE_N / 4; i += blockDim.x)
            dst[i] = src[i];
    }
    __syncthreads();

    const int stride = gridDim.x * blockDim.x;
    for (int e = blockIdx.x * blockDim.x + threadIdx.x; e < n; e += stride) {
        float xv = x[e];
        float u  = (xv - XMIN) * INV_H;
        float fi = floorf(u);
        int   i0 = (int)fi;
        float r;
        if (i0 >= 1 && i0 <= TABLE_N - 3) {
            float s  = u - fi;                 // in [0,1)
            float p0 = st[i0 - 1];
            float p1 = st[i0];
            float p2 = st[i0 + 1];
            float p3 = st[i0 + 2];
            // Cubic Lagrange through nodes at -1,0,1,2 (O(h^4) accuracy)
            float sm1 = s - 1.0f, sm2 = s - 2.0f, sp1 = s + 1.0f;
            float c0 = -0.16666666666666666f * s   * sm1 * sm2;
            float c1 =  0.5f                 * sp1 * sm1 * sm2;
            float c2 = -0.5f                 * sp1 * s   * sm2;
            float c3 =  0.16666666666666666f * sp1 * s   * sm1;
            r = c0 * p0 + c1 * p1 + c2 * p2 + c3 * p3;
        } else {
            r = eval_full(xv, w1, b1, w2, b2, w3, b3, w4, b4);
        }
        out[e] = r;
    }
}

// ---------------------------------------------------------------------------
// Launch
// ---------------------------------------------------------------------------
extern "C" void kernel_launch(void* const* d_in, const int* in_sizes, int n_in,
                              void* d_out, int out_size)
{
    const float* x  = (const float*)d_in[0];
    const float* w1 = (const float*)d_in[1];
    const float* b1 = (const float*)d_in[2];
    const float* w2 = (const float*)d_in[3];
    const float* b2 = (const float*)d_in[4];
    const float* w3 = (const float*)d_in[5];
    const float* b3 = (const float*)d_in[6];
    const float* w4 = (const float*)d_in[7];
    const float* b4 = (const float*)d_in[8];
    float* out = (float*)d_out;
    const int n = in_sizes[0];

    build_table_kernel<<<TABLE_N / 8, 256>>>(w1, b1, w2, b2, w3, b3, w4, b4);
    apply_kernel<<<512, 256>>>(x, out, n, w1, b1, w2, b2, w3, b3, w4, b4);
}

// round 5
// speedup vs baseline: 2.3751x; 2.3751x over previous
#include <cuda_runtime.h>
#include <math.h>

// ---------------------------------------------------------------------------
// PolyNetFP4Sim: x (B,1) -> 64 -> 64 -> 32 -> 1 MLP, FP4-quantized weights.
// Input is scalar per sample => the net is a smooth 1-D function f(x).
//   K0: quantize weights ONCE into __device__ globals (transposed for smem).
//   K1: tabulate f on 4096 uniform points over [-6, 6].
//   K2: per-sample cubic Lagrange interpolation, float4 per thread.
// |x| > ~5.99 (never for this dataset) falls back to direct evaluation.
// ---------------------------------------------------------------------------

#define TABLE_N 4096
#define XMIN    (-6.0f)
#define H_STEP  (0.0029296875f)            // 12/4096 exact in fp32
#define INV_H   (341.33333333333333f)      // 4096/12

__device__ float g_table[TABLE_N];
__device__ float g_qw1[64];
__device__ float g_qw2T[64 * 64];          // [k][j]
__device__ float g_qw3T[64 * 32];          // [k][j]
__device__ float g_qw4[32];

__device__ __forceinline__ float quant4(float w) {
    if (w == 0.0f) return 0.0f;
    int e;
    float m = frexpf(fabsf(w), &e);             // m in [0.5, 1)
    int qe = e + 1;
    qe = qe < 0 ? 0 : (qe > 3 ? 3 : qe);
    float qm = (m >= 0.75f) ? 0.5f : 0.0f;
    float val = ldexpf((1.0f + qm) * 0.5f, qe - 1);
    return copysignf(val, w);
}

__device__ __forceinline__ float silu(float x) {
    return x / (1.0f + expf(-x));
}

// Cold-path full evaluation from raw weights (|x| outside table range).
__device__ __noinline__ float eval_full(
    float x,
    const float* w1, const float* b1,
    const float* w2, const float* b2,
    const float* w3, const float* b3,
    const float* w4, const float* b4)
{
    float h1[64], h2[64];
    for (int j = 0; j < 64; j++)
        h1[j] = silu(fmaf(x, quant4(w1[j]), b1[j]));
    for (int j = 0; j < 64; j++) {
        float a = b2[j];
        for (int k = 0; k < 64; k++)
            a = fmaf(h1[k], quant4(w2[j * 64 + k]), a);
        h2[j] = silu(a);
    }
    float acc = b4[0];
    for (int j = 0; j < 32; j++) {
        float a = b3[j];
        for (int k = 0; k < 64; k++)
            a = fmaf(h2[k], quant4(w3[j * 64 + k]), a);
        acc = fmaf(silu(a), quant4(w4[j]), acc);
    }
    return acc;
}

// ---------------------------------------------------------------------------
// K0: quantize all weights exactly once, transposing w2/w3 for the build.
// ---------------------------------------------------------------------------
__global__ void __launch_bounds__(256)
quantize_kernel(const float* __restrict__ w1, const float* __restrict__ w2,
                const float* __restrict__ w3, const float* __restrict__ w4)
{
    const int tid = blockIdx.x * blockDim.x + threadIdx.x;
    const int stride = gridDim.x * blockDim.x;
    for (int i = tid; i < 64; i += stride)   g_qw1[i] = quant4(w1[i]);
    for (int i = tid; i < 4096; i += stride) {
        int j = i >> 6, k = i & 63;
        g_qw2T[k * 64 + j] = quant4(w2[i]);
    }
    for (int i = tid; i < 2048; i += stride) {
        int j = i >> 6, k = i & 63;
        g_qw3T[k * 32 + j] = quant4(w3[i]);
    }
    for (int i = tid; i < 32; i += stride)   g_qw4[i] = quant4(w4[i]);
}

// ---------------------------------------------------------------------------
// K1: build table. 64 blocks x 8 warps x 8 entries/warp = 4096 entries.
// Pre-quantized weights copied to shared (float4); biases loaded direct.
// ---------------------------------------------------------------------------
#define ENT_PER_WARP 8
#define WARPS_PER_BLOCK 8
#define ENT_PER_BLOCK (ENT_PER_WARP * WARPS_PER_BLOCK)

__global__ void __launch_bounds__(256)
build_table_kernel(
    const float* __restrict__ b1, const float* __restrict__ b2,
    const float* __restrict__ b3, const float* __restrict__ b4)
{
    __shared__ float sw1[64], sb1[64], sb2[64], sb3[32], sw4[32];
    __shared__ float sw2T[64 * 64];
    __shared__ float sw3T[64 * 32];
    __shared__ float sh1[WARPS_PER_BLOCK][64];
    __shared__ float sh2[WARPS_PER_BLOCK][64];

    const int tid = threadIdx.x;

    for (int i = tid; i < 64; i += blockDim.x) {
        sw1[i] = g_qw1[i];
        sb1[i] = b1[i];
        sb2[i] = b2[i];
    }
    for (int i = tid; i < 32; i += blockDim.x) {
        sb3[i] = b3[i];
        sw4[i] = g_qw4[i];
    }
    {
        float4*       d2 = reinterpret_cast<float4*>(sw2T);
        const float4* s2 = reinterpret_cast<const float4*>(g_qw2T);
        for (int i = tid; i < 64 * 64 / 4; i += blockDim.x) d2[i] = s2[i];
        float4*       d3 = reinterpret_cast<float4*>(sw3T);
        const float4* s3 = reinterpret_cast<const float4*>(g_qw3T);
        for (int i = tid; i < 64 * 32 / 4; i += blockDim.x) d3[i] = s3[i];
    }
    __syncthreads();

    const int warp = tid >> 5;
    const int lane = tid & 31;
    const float b4v = b4[0];

    const int base = blockIdx.x * ENT_PER_BLOCK + warp * ENT_PER_WARP;

    #pragma unroll 1
    for (int i = 0; i < ENT_PER_WARP; i++) {
        const int entry = base + i;
        const float x = XMIN + (float)entry * H_STEP;

        // layer 1: 64 outputs, 2 per lane
        sh1[warp][lane]      = silu(fmaf(x, sw1[lane],      sb1[lane]));
        sh1[warp][lane + 32] = silu(fmaf(x, sw1[lane + 32], sb1[lane + 32]));
        __syncwarp();

        // layer 2: 64x64; lane j -> outputs j, j+32
        float a0 = sb2[lane];
        float a1 = sb2[lane + 32];
        #pragma unroll
        for (int k = 0; k < 64; k++) {
            float h = sh1[warp][k];
            a0 = fmaf(h, sw2T[k * 64 + lane],      a0);
            a1 = fmaf(h, sw2T[k * 64 + lane + 32], a1);
        }
        sh2[warp][lane]      = silu(a0);
        sh2[warp][lane + 32] = silu(a1);
        __syncwarp();

        // layer 3: 32x64; lane j -> output j
        float c = sb3[lane];
        #pragma unroll
        for (int k = 0; k < 64; k++)
            c = fmaf(sh2[warp][k], sw3T[k * 32 + lane], c);
        float h3 = silu(c);

        // layer 4: warp-reduced dot with w4
        float p = h3 * sw4[lane];
        #pragma unroll
        for (int off = 16; off; off >>= 1)
            p += __shfl_xor_sync(0xffffffffu, p, off);

        if (lane == 0)
            g_table[entry] = p + b4v;
        __syncwarp();
    }
}

// ---------------------------------------------------------------------------
// K2: apply. 16KB table in shared; one float4 of x per thread (4-way ILP).
// ---------------------------------------------------------------------------
__device__ __forceinline__ float interp_one(
    const float* __restrict__ st, float xv,
    const float* w1, const float* b1, const float* w2, const float* b2,
    const float* w3, const float* b3, const float* w4, const float* b4)
{
    float u  = (xv - XMIN) * INV_H;
    float fi = floorf(u);
    int   i0 = (int)fi;
    if (i0 >= 1 && i0 <= TABLE_N - 3) {
        float s  = u - fi;
        float p0 = st[i0 - 1];
        float p1 = st[i0];
        float p2 = st[i0 + 1];
        float p3 = st[i0 + 2];
        float sm1 = s - 1.0f, sm2 = s - 2.0f, sp1 = s + 1.0f;
        float c0 = -0.16666666666666666f * s   * sm1 * sm2;
        float c1 =  0.5f                 * sp1 * sm1 * sm2;
        float c2 = -0.5f                 * sp1 * s   * sm2;
        float c3 =  0.16666666666666666f * sp1 * s   * sm1;
        return c0 * p0 + c1 * p1 + c2 * p2 + c3 * p3;
    }
    return eval_full(xv, w1, b1, w2, b2, w3, b3, w4, b4);
}

__global__ void __launch_bounds__(256)
apply_kernel(
    const float* __restrict__ x, float* __restrict__ out, int n,
    const float* __restrict__ w1, const float* __restrict__ b1,
    const float* __restrict__ w2, const float* __restrict__ b2,
    const float* __restrict__ w3, const float* __restrict__ b3,
    const float* __restrict__ w4, const float* __restrict__ b4)
{
    __shared__ float st[TABLE_N];
    {
        float4*       dst = reinterpret_cast<float4*>(st);
        const float4* src = reinterpret_cast<const float4*>(g_table);
        for (int i = threadIdx.x; i < TABLE_N / 4; i += blockDim.x)
            dst[i] = src[i];
    }
    __syncthreads();

    const int gid = blockIdx.x * blockDim.x + threadIdx.x;
    const int e0  = gid * 4;

    if (e0 + 3 < n) {
        float4 xv = *reinterpret_cast<const float4*>(x + e0);
        float4 r;
        r.x = interp_one(st, xv.x, w1, b1, w2, b2, w3, b3, w4, b4);
        r.y = interp_one(st, xv.y, w1, b1, w2, b2, w3, b3, w4, b4);
        r.z = interp_one(st, xv.z, w1, b1, w2, b2, w3, b3, w4, b4);
        r.w = interp_one(st, xv.w, w1, b1, w2, b2, w3, b3, w4, b4);
        *reinterpret_cast<float4*>(out + e0) = r;
    } else {
        for (int e = e0; e < n; e++)
            out[e] = interp_one(st, x[e], w1, b1, w2, b2, w3, b3, w4, b4);
    }
}

// ---------------------------------------------------------------------------
// Launch
// ---------------------------------------------------------------------------
extern "C" void kernel_launch(void* const* d_in, const int* in_sizes, int n_in,
                              void* d_out, int out_size)
{
    const float* x  = (const float*)d_in[0];
    const float* w1 = (const float*)d_in[1];
    const float* b1 = (const float*)d_in[2];
    const float* w2 = (const float*)d_in[3];
    const float* b2 = (const float*)d_in[4];
    const float* w3 = (const float*)d_in[5];
    const float* b3 = (const float*)d_in[6];
    const float* w4 = (const float*)d_in[7];
    const float* b4 = (const float*)d_in[8];
    float* out = (float*)d_out;
    const int n = in_sizes[0];

    quantize_kernel<<<8, 256>>>(w1, w2, w3, w4);
    build_table_kernel<<<TABLE_N / ENT_PER_BLOCK, 256>>>(b1, b2, b3, b4);

    const int nvec = (n + 3) / 4;
    const int blocks = (nvec + 255) / 256;
    apply_kernel<<<blocks, 256>>>(x, out, n, w1, b1, w2, b2, w3, b3, w4, b4);
}

// round 6
// speedup vs baseline: 3.3959x; 1.4298x over previous
#include <cuda_runtime.h>
#include <math.h>

// ---------------------------------------------------------------------------
// PolyNetFP4Sim: x (B,1) -> 64 -> 64 -> 32 -> 1 MLP, FP4-quantized weights.
// Scalar input per sample => the whole net is a smooth 1-D function f(x).
//   K1: build: quantize weights in-block (bitwise quant4) and tabulate f on
//       2048 points over [-6,6], writing an OVERLAPPED float4 stencil table
//       st4[i] = (t[i-1], t[i], t[i+1], t[i+2]).
//   K2: apply: cubic Lagrange interpolation; ONE LDS.128 per element.
// |x| outside the table (never for this dataset) -> direct evaluation.
// ---------------------------------------------------------------------------

#define TABLE_N 2048
#define XMIN    (-6.0f)
#define H_STEP  (0.005859375f)             // 12/2048 exact in fp32
#define INV_H   (170.66666666666666f)      // 2048/12

__device__ float g_t4[4 * TABLE_N];        // overlapped stencil table (float4 flat)

// Branch-free FP4 quantization (matches frexp/ldexp reference for normals;
// denormal/zero guarded — unreachable for N(0,0.1) weights but correct).
__device__ __forceinline__ float quant4(float w) {
    unsigned a   = __float_as_uint(w);
    unsigned ab  = a & 0x7fffffffu;
    if (ab < 0x00800000u) {                 // zero or denormal (cold)
        if (ab == 0u) return 0.0f;
        int e; float m = frexpf(fabsf(w), &e);
        int qe = e + 1; qe = qe < 0 ? 0 : (qe > 3 ? 3 : qe);
        return copysignf(ldexpf((m >= 0.75f ? 1.5f : 1.0f) * 0.5f, qe - 1), w);
    }
    int ef = (int)(ab >> 23) - 127;
    int qe = ef + 2;
    qe = qe < 0 ? 0 : (qe > 3 ? 3 : qe);
    float base = __uint_as_float((unsigned)(125 + qe) << 23);   // 2^(qe-2)
    float val  = (ab & 0x00400000u) ? 1.5f * base : base;       // m >= 0.75
    return copysignf(val, w);
}

__device__ __forceinline__ float silu(float x) {
    return x / (1.0f + expf(-x));
}

// Cold-path full evaluation (|x| outside table range; never for this dataset).
__device__ __noinline__ float eval_full(
    float x,
    const float* w1, const float* b1,
    const float* w2, const float* b2,
    const float* w3, const float* b3,
    const float* w4, const float* b4)
{
    float h1[64], h2[64];
    for (int j = 0; j < 64; j++)
        h1[j] = silu(fmaf(x, quant4(w1[j]), b1[j]));
    for (int j = 0; j < 64; j++) {
        float a = b2[j];
        for (int k = 0; k < 64; k++)
            a = fmaf(h1[k], quant4(w2[j * 64 + k]), a);
        h2[j] = silu(a);
    }
    float acc = b4[0];
    for (int j = 0; j < 32; j++) {
        float a = b3[j];
        for (int k = 0; k < 64; k++)
            a = fmaf(h2[k], quant4(w3[j * 64 + k]), a);
        acc = fmaf(silu(a), quant4(w4[j]), acc);
    }
    return acc;
}

// ---------------------------------------------------------------------------
// K1: build. 128 blocks x 8 warps x 2 entries/warp = 2048 entries.
// Weights quantized in-block (cheap bitwise quant4) into PADDED shared arrays
// (stride 65 / 33 -> conflict-free STS and LDS).
// ---------------------------------------------------------------------------
#define ENT_PER_WARP 2
#define WARPS_PER_BLOCK 8
#define ENT_PER_BLOCK (ENT_PER_WARP * WARPS_PER_BLOCK)

__global__ void __launch_bounds__(256)
build_table_kernel(
    const float* __restrict__ w1, const float* __restrict__ b1,
    const float* __restrict__ w2, const float* __restrict__ b2,
    const float* __restrict__ w3, const float* __restrict__ b3,
    const float* __restrict__ w4, const float* __restrict__ b4)
{
    __shared__ float sw1[64], sb1[64], sb2[64], sb3[32], sw4[32];
    __shared__ float sw2T[64 * 65];                 // [k][j], padded
    __shared__ float sw3T[64 * 33];                 // [k][j], padded
    __shared__ float sh1[WARPS_PER_BLOCK][64];
    __shared__ float sh2[WARPS_PER_BLOCK][64];

    const int tid = threadIdx.x;

    for (int i = tid; i < 64; i += 256) {
        sw1[i] = quant4(w1[i]);
        sb1[i] = b1[i];
        sb2[i] = b2[i];
    }
    for (int i = tid; i < 32; i += 256) {
        sb3[i] = b3[i];
        sw4[i] = quant4(w4[i]);
    }
    for (int i = tid; i < 64 * 64; i += 256) {      // coalesced LDG; pad kills STS conflicts
        int j = i >> 6, k = i & 63;
        sw2T[k * 65 + j] = quant4(w2[i]);
    }
    for (int i = tid; i < 32 * 64; i += 256) {
        int j = i >> 6, k = i & 63;
        sw3T[k * 33 + j] = quant4(w3[i]);
    }
    __syncthreads();

    const int warp = tid >> 5;
    const int lane = tid & 31;
    const float b4v = b4[0];

    const int base = blockIdx.x * ENT_PER_BLOCK + warp * ENT_PER_WARP;

    #pragma unroll 1
    for (int i = 0; i < ENT_PER_WARP; i++) {
        const int e = base + i;
        const float x = XMIN + (float)e * H_STEP;

        // layer 1
        sh1[warp][lane]      = silu(fmaf(x, sw1[lane],      sb1[lane]));
        sh1[warp][lane + 32] = silu(fmaf(x, sw1[lane + 32], sb1[lane + 32]));
        __syncwarp();

        // layer 2: lane j -> outputs j, j+32
        float a0 = sb2[lane];
        float a1 = sb2[lane + 32];
        #pragma unroll
        for (int k = 0; k < 64; k++) {
            float h = sh1[warp][k];
            a0 = fmaf(h, sw2T[k * 65 + lane],      a0);
            a1 = fmaf(h, sw2T[k * 65 + lane + 32], a1);
        }
        sh2[warp][lane]      = silu(a0);
        sh2[warp][lane + 32] = silu(a1);
        __syncwarp();

        // layer 3
        float c = sb3[lane];
        #pragma unroll
        for (int k = 0; k < 64; k++)
            c = fmaf(sh2[warp][k], sw3T[k * 33 + lane], c);
        float h3 = silu(c);

        // layer 4: warp reduction
        float p = h3 * sw4[lane];
        #pragma unroll
        for (int off = 16; off; off >>= 1)
            p += __shfl_xor_sync(0xffffffffu, p, off);

        if (lane == 0) {
            float t = p + b4v;
            // scatter into overlapped stencil table: st4[i] = t[i-1..i+2]
            if (e + 1 <= TABLE_N - 1) g_t4[4 * (e + 1) + 0] = t;
            g_t4[4 * e + 1] = t;
            if (e >= 1)               g_t4[4 * (e - 1) + 2] = t;
            if (e >= 2)               g_t4[4 * (e - 2) + 3] = t;
        }
        __syncwarp();
    }
}

// ---------------------------------------------------------------------------
// K2: apply. 32KB stencil table in shared; single LDS.128 per element.
// 8 elements per thread (2 float4 groups) for ILP; grid 512.
// ---------------------------------------------------------------------------
__device__ __forceinline__ float interp_one(
    const float4* __restrict__ st4, float xv,
    const float* w1, const float* b1, const float* w2, const float* b2,
    const float* w3, const float* b3, const float* w4, const float* b4)
{
    float u  = (xv - XMIN) * INV_H;
    float fi = floorf(u);
    int   i0 = (int)fi;
    if (i0 >= 1 && i0 <= TABLE_N - 3) {
        float s = u - fi;
        float4 q = st4[i0];                 // (t[i0-1], t[i0], t[i0+1], t[i0+2])
        float sm1 = s - 1.0f, sm2 = s - 2.0f, sp1 = s + 1.0f;
        float c0 = -0.16666666666666666f * s   * sm1 * sm2;
        float c1 =  0.5f                 * sp1 * sm1 * sm2;
        float c2 = -0.5f                 * sp1 * s   * sm2;
        float c3 =  0.16666666666666666f * sp1 * s   * sm1;
        return c0 * q.x + c1 * q.y + c2 * q.z + c3 * q.w;
    }
    return eval_full(xv, w1, b1, w2, b2, w3, b3, w4, b4);
}

__global__ void __launch_bounds__(256)
apply_kernel(
    const float* __restrict__ x, float* __restrict__ out, int n,
    const float* __restrict__ w1, const float* __restrict__ b1,
    const float* __restrict__ w2, const float* __restrict__ b2,
    const float* __restrict__ w3, const float* __restrict__ b3,
    const float* __restrict__ w4, const float* __restrict__ b4)
{
    __shared__ float4 st4[TABLE_N];
    {
        const float4* src = reinterpret_cast<const float4*>(g_t4);
        for (int i = threadIdx.x; i < TABLE_N; i += 256)
            st4[i] = src[i];
    }
    __syncthreads();

    const int gid = blockIdx.x * blockDim.x + threadIdx.x;
    const int e0  = gid * 8;

    if (e0 + 7 < n) {
        float4 xa = *reinterpret_cast<const float4*>(x + e0);
        float4 xb = *reinterpret_cast<const float4*>(x + e0 + 4);
        float4 ra, rb;
        ra.x = interp_one(st4, xa.x, w1, b1, w2, b2, w3, b3, w4, b4);
        ra.y = interp_one(st4, xa.y, w1, b1, w2, b2, w3, b3, w4, b4);
        ra.z = interp_one(st4, xa.z, w1, b1, w2, b2, w3, b3, w4, b4);
        ra.w = interp_one(st4, xa.w, w1, b1, w2, b2, w3, b3, w4, b4);
        rb.x = interp_one(st4, xb.x, w1, b1, w2, b2, w3, b3, w4, b4);
        rb.y = interp_one(st4, xb.y, w1, b1, w2, b2, w3, b3, w4, b4);
        rb.z = interp_one(st4, xb.z, w1, b1, w2, b2, w3, b3, w4, b4);
        rb.w = interp_one(st4, xb.w, w1, b1, w2, b2, w3, b3, w4, b4);
        *reinterpret_cast<float4*>(out + e0)     = ra;
        *reinterpret_cast<float4*>(out + e0 + 4) = rb;
    } else {
        for (int e = e0; e < n; e++)
            out[e] = interp_one(st4, x[e], w1, b1, w2, b2, w3, b3, w4, b4);
    }
}

// ---------------------------------------------------------------------------
// Launch
// ---------------------------------------------------------------------------
extern "C" void kernel_launch(void* const* d_in, const int* in_sizes, int n_in,
                              void* d_out, int out_size)
{
    const float* x  = (const float*)d_in[0];
    const float* w1 = (const float*)d_in[1];
    const float* b1 = (const float*)d_in[2];
    const float* w2 = (const float*)d_in[3];
    const float* b2 = (const float*)d_in[4];
    const float* w3 = (const float*)d_in[5];
    const float* b3 = (const float*)d_in[6];
    const float* w4 = (const float*)d_in[7];
    const float* b4 = (const float*)d_in[8];
    float* out = (float*)d_out;
    const int n = in_sizes[0];

    build_table_kernel<<<TABLE_N / ENT_PER_BLOCK, 256>>>(w1, b1, w2, b2, w3, b3, w4, b4);

    const int nvec   = (n + 7) / 8;
    const int blocks = (nvec + 255) / 256;
    apply_kernel<<<blocks, 256>>>(x, out, n, w1, b1, w2, b2, w3, b3, w4, b4);
}